// round 5
// baseline (speedup 1.0000x reference)
#include <cuda_runtime.h>
#include <cuda_bf16.h>

// Problem constants (fixed by the reference)
#define BB 2
#define CC 64
#define HH 512
#define WW 512
#define HW (HH * WW)          // 262144
#define NN 4096
#define KK 5
#define NPAIR (BB * NN)       // 8192
#define INV_MAXDIST (1.0f / 724.07733f)
#define FEAT_THRESH_NOMATCH 16.0f
#define FINAL_SCALE (1.0f / ((KK + 1.0f) * NN))   // 1/24576

// Scratch (allocation-free rule: __device__ globals)
__device__ float g_fr[NPAIR * CC];     // compacted ref features   [b][i][c]
__device__ float g_fo[NPAIR * CC];     // compacted other features [b][i][c]
__device__ float g_partial[NPAIR];     // per-match loss partial
__device__ int   g_order[4][NN];       // per set: packed (lin<<12 | point id)

// ---------------------------------------------------------------------------
// Kernel S: counting sort of the 4 point sets (ref b0/b1, oth b0/b1) by y-row.
// One block of 1024 threads per set. Output: g_order[set][pos] = lin<<12 | id,
// ascending-ish in lin (bucketed by y; within-row order arbitrary -> value-
// deterministic downstream since results are written per-id).
// ---------------------------------------------------------------------------
__global__ void __launch_bounds__(1024) sort_kernel(
        const int* __restrict__ inds_ref,
        const int* __restrict__ inds_other) {
    int s = blockIdx.x;           // 0,1 = ref b0,b1 ; 2,3 = oth b0,b1
    int t = s >> 1, b = s & 1;
    const int* inds = t ? inds_other : inds_ref;

    __shared__ int lin_s[NN];         // 16 KB
    __shared__ int hist[512];
    __shared__ int sc[2][512];
    __shared__ int offs[512];

    for (int k = threadIdx.x; k < 512; k += 1024) hist[k] = 0;
    __syncthreads();

    for (int i = threadIdx.x; i < NN; i += 1024) {
        int x = inds[b * 2 * NN + i];
        int y = inds[b * 2 * NN + NN + i];
        int lin = (y << 9) | x;       // 512*y + x
        lin_s[i] = lin;
        atomicAdd(&hist[y], 1);
    }
    __syncthreads();

    // inclusive scan of hist[512] (Hillis-Steele, threads 0..511 active)
    if (threadIdx.x < 512) sc[0][threadIdx.x] = hist[threadIdx.x];
    __syncthreads();
    int p = 0;
#pragma unroll
    for (int d = 1; d < 512; d <<= 1) {
        if (threadIdx.x < 512) {
            int v = sc[p][threadIdx.x];
            if ((int)threadIdx.x >= d) v += sc[p][threadIdx.x - d];
            sc[p ^ 1][threadIdx.x] = v;
        }
        __syncthreads();
        p ^= 1;
    }
    if (threadIdx.x < 512)
        offs[threadIdx.x] = sc[p][threadIdx.x] - hist[threadIdx.x];  // exclusive
    __syncthreads();

    for (int i = threadIdx.x; i < NN; i += 1024) {
        int lin = lin_s[i];
        int pos = atomicAdd(&offs[lin >> 9], 1);
        g_order[s][pos] = (lin << 12) | i;
    }
}

// ---------------------------------------------------------------------------
// Kernel A: sorted gather. warp <-> (set, channel-group, chunk of 32 sorted
// points). Per load-slot a warp reads 32 ascending addresses in one plane ->
// DRAM row-buffer hits + coalescer line merges. Each thread: 4 loads
// (channels 4q..4q+3), one scattered float4 store to the compact array.
// ---------------------------------------------------------------------------
__global__ void __launch_bounds__(256) gather_sorted_kernel(
        const float* __restrict__ ref,
        const float* __restrict__ oth) {
    int gw   = (blockIdx.x * blockDim.x + threadIdx.x) >> 5;  // 0..8191
    int lane = threadIdx.x & 31;
    int s    = gw >> 11;          // set (4)
    int qg   = (gw >> 7) & 15;    // channel group (16)
    int chnk = gw & 127;          // sorted chunk (128)
    int t = s >> 1, b = s & 1;

    int packed = g_order[s][chnk * 32 + lane];
    int lin = packed >> 12;
    int id  = packed & 4095;

    const float* src = (t ? oth : ref) + (size_t)(b * CC + 4 * qg) * HW + lin;
    float v0 = __ldg(src + 0 * HW);
    float v1 = __ldg(src + 1 * HW);
    float v2 = __ldg(src + 2 * HW);
    float v3 = __ldg(src + 3 * HW);

    float* dst = (t ? g_fo : g_fr) + (size_t)((b << 12) | id) * CC + 4 * qg;
    *reinterpret_cast<float4*>(dst) = make_float4(v0, v1, v2, v3);
}

// ---------------------------------------------------------------------------
// Kernel B: one warp per match pair; all feature reads coalesced from the
// compact arrays (~4 MB, L2-resident).
// ---------------------------------------------------------------------------
__global__ void __launch_bounds__(256) match_kernel(
        const float* __restrict__ weights,
        const int* __restrict__ inds_ref,
        const int* __restrict__ rand_inds) {
    int gwarp = (blockIdx.x * blockDim.x + threadIdx.x) >> 5;
    int lane  = threadIdx.x & 31;
    if (gwarp >= NPAIR) return;
    int b = gwarp >> 12;
    int i = gwarp & (NN - 1);

    const float2* frp = reinterpret_cast<const float2*>(g_fr + (size_t)gwarp * CC);
    const float2* fop = reinterpret_cast<const float2*>(g_fo + (size_t)gwarp * CC);
    float2 fr = frp[lane];
    float2 fo = fop[lane];
    float d0 = fr.x - fo.x, d1 = fr.y - fo.y;
    float sm = d0 * d0 + d1 * d1;

    int   jarr[KK];
    float sk[KK];
    const int* ri = rand_inds + (size_t)gwarp * KK;
#pragma unroll
    for (int k = 0; k < KK; k++) {
        int j = __ldg(ri + k);             // uniform across warp (broadcast)
        jarr[k] = j;
        const float2* fo_j =
            reinterpret_cast<const float2*>(g_fo + (size_t)(b * NN + j) * CC);
        float2 fj = fo_j[lane];
        float e0 = fr.x - fj.x, e1 = fr.y - fj.y;
        sk[k] = e0 * e0 + e1 * e1;
    }

#pragma unroll
    for (int off = 16; off > 0; off >>= 1) {
        sm += __shfl_down_sync(0xFFFFFFFFu, sm, off);
#pragma unroll
        for (int k = 0; k < KK; k++)
            sk[k] += __shfl_down_sync(0xFFFFFFFFu, sk[k], off);
    }

    if (lane == 0) {
        int xr = inds_ref[b * 2 * NN + i];
        int yr = inds_ref[b * 2 * NN + NN + i];
        float total = weights[b * NN + i] * fmaxf(sm, 0.0f);
#pragma unroll
        for (int k = 0; k < KK; k++) {
            int j  = jarr[k];
            float xj = (float)inds_ref[b * 2 * NN + j];
            float yj = (float)inds_ref[b * 2 * NN + NN + j];
            float dx = (float)xr - xj;
            float dy = (float)yr - yj;
            float dist = sqrtf(dx * dx + dy * dy);
            total += (-dist * INV_MAXDIST) * fminf(sk[k], FEAT_THRESH_NOMATCH);
        }
        g_partial[gwarp] = total * FINAL_SCALE;
    }
}

// ---------------------------------------------------------------------------
// Kernel C: deterministic single-block reduction of the 8192 partials.
// ---------------------------------------------------------------------------
__global__ void reduce_kernel(float* __restrict__ out) {
    __shared__ float s[256];
    float acc = 0.0f;
    for (int idx = threadIdx.x; idx < NPAIR; idx += 256)
        acc += g_partial[idx];
    s[threadIdx.x] = acc;
    __syncthreads();
#pragma unroll
    for (int stride = 128; stride > 0; stride >>= 1) {
        if (threadIdx.x < stride) s[threadIdx.x] += s[threadIdx.x + stride];
        __syncthreads();
    }
    if (threadIdx.x == 0) out[0] = s[0];
}

extern "C" void kernel_launch(void* const* d_in, const int* in_sizes, int n_in,
                              void* d_out, int out_size) {
    const float* inputs_ref   = (const float*)d_in[0];
    const float* inputs_other = (const float*)d_in[1];
    const float* weights      = (const float*)d_in[2];
    const int*   inds_ref     = (const int*)d_in[3];
    const int*   inds_other   = (const int*)d_in[4];
    const int*   rand_inds    = (const int*)d_in[5];
    float* out = (float*)d_out;

    sort_kernel<<<4, 1024>>>(inds_ref, inds_other);
    // 8192 warps total -> 1024 blocks of 8 warps
    gather_sorted_kernel<<<1024, 256>>>(inputs_ref, inputs_other);
    match_kernel<<<(NPAIR * 32 + 255) / 256, 256>>>(weights, inds_ref, rand_inds);
    reduce_kernel<<<1, 256>>>(out);
}